// round 1
// baseline (speedup 1.0000x reference)
#include <cuda_runtime.h>
#include <cstdint>

// MoEVM_62380105007239 — soft-ALU over one-hot byte encodings.
// Exact-equivalent computation: per batch element, decode 4 one-hot bytes of
// a and b into u32s (little-endian), compute u32 add (wraps naturally, which
// matches the 4-byte nibble carry chain) and byte-wise XOR, then emit the
// near-one-hot output distributions the reference's SCALE=100 softmaxes
// produce: 1.0 at the result byte, exp(-100) (fp32 subnormal) at bytes
// sharing a nibble with it, 0 elsewhere.

static __device__ __forceinline__ float onehot_val(int j, int s, float tiny) {
    if (j == s) return 1.0f;
    if (((j ^ s) & 0xF0) == 0 || ((j ^ s) & 0x0F) == 0) return tiny;
    return 0.0f;
}

__global__ void __launch_bounds__(256, 4) moe_alu_kernel(
    const float* __restrict__ a,
    const float* __restrict__ b,
    float* __restrict__ out,
    int B)
{
    const int warp = (blockIdx.x * blockDim.x + threadIdx.x) >> 5;
    const int lane = threadIdx.x & 31;
    if (warp >= B) return;

    const float4* __restrict__ pa =
        reinterpret_cast<const float4*>(a + (size_t)warp * 1024);
    const float4* __restrict__ pb =
        reinterpret_cast<const float4*>(b + (size_t)warp * 1024);

    // Decode: each lane scans 8 float4s of a and 8 of b (16 independent
    // loads -> high MLP). One-hot value 1.0 marks the byte index.
    unsigned va = 0, vb = 0;
    #pragma unroll
    for (int r = 0; r < 8; r++) {
        const int f4   = lane + 32 * r;        // float4 index within [4][256]
        const int base = f4 * 4;               // flat float index 0..1023
        const int sh   = (base >> 8) * 8;      // byte slot shift (vector i)
        const int j    = base & 255;           // byte value of component .x
        const float4 xa = pa[f4];
        const float4 xb = pb[f4];
        if (xa.x > 0.5f) va |= (unsigned)(j    ) << sh;
        if (xa.y > 0.5f) va |= (unsigned)(j + 1) << sh;
        if (xa.z > 0.5f) va |= (unsigned)(j + 2) << sh;
        if (xa.w > 0.5f) va |= (unsigned)(j + 3) << sh;
        if (xb.x > 0.5f) vb |= (unsigned)(j    ) << sh;
        if (xb.y > 0.5f) vb |= (unsigned)(j + 1) << sh;
        if (xb.z > 0.5f) vb |= (unsigned)(j + 2) << sh;
        if (xb.w > 0.5f) vb |= (unsigned)(j + 3) << sh;
    }
    va = __reduce_or_sync(0xFFFFFFFFu, va);
    vb = __reduce_or_sync(0xFFFFFFFFu, vb);

    const unsigned vsum = va + vb;   // 4-byte LE carry chain == u32 add
    const unsigned vxor = va ^ vb;

    // exp(-100) in fp32 (subnormal); literal rounds to nearest representable.
    const float TINY = 3.7200760e-44f;

    float4* __restrict__ po_add =
        reinterpret_cast<float4*>(out + (size_t)warp * 1024);
    float4* __restrict__ po_xor =
        reinterpret_cast<float4*>(out + ((size_t)B + warp) * 1024);

    #pragma unroll
    for (int r = 0; r < 8; r++) {
        const int f4   = lane + 32 * r;
        const int base = f4 * 4;
        const int sh   = (base >> 8) * 8;
        const int j    = base & 255;
        const int ss   = (int)((vsum >> sh) & 255u);
        const int xs   = (int)((vxor >> sh) & 255u);
        float4 oa, ox;
        oa.x = onehot_val(j    , ss, TINY);
        oa.y = onehot_val(j + 1, ss, TINY);
        oa.z = onehot_val(j + 2, ss, TINY);
        oa.w = onehot_val(j + 3, ss, TINY);
        ox.x = onehot_val(j    , xs, TINY);
        ox.y = onehot_val(j + 1, xs, TINY);
        ox.z = onehot_val(j + 2, xs, TINY);
        ox.w = onehot_val(j + 3, xs, TINY);
        po_add[f4] = oa;
        po_xor[f4] = ox;
    }
}

extern "C" void kernel_launch(void* const* d_in, const int* in_sizes, int n_in,
                              void* d_out, int out_size)
{
    const float* a = (const float*)d_in[0];
    const float* b = (const float*)d_in[1];
    float* out = (float*)d_out;

    const int B = in_sizes[0] / 1024;          // [B,4,256] floats
    const int threads = 256;                   // 8 warps/block
    const int blocks = (B * 32 + threads - 1) / threads;
    moe_alu_kernel<<<blocks, threads>>>(a, b, out, B);
}

// round 2
// speedup vs baseline: 1.0151x; 1.0151x over previous
#include <cuda_runtime.h>
#include <cstdint>

// MoEVM_62380105007239 — soft-ALU over one-hot byte encodings.
// Per batch element: decode 4 one-hot bytes of a,b into u32 (little-endian),
// u32 add (== the 4-byte nibble carry chain) and bytewise XOR, then emit the
// near-one-hot distributions the SCALE=100 softmaxes produce: 1.0 at the
// result byte, exp(-100) (fp32 subnormal) at bytes sharing a nibble, else 0.
//
// R2: decode via FMA dot-product (one-hot * index == index), offloading the
// alu pipe and cutting register pressure so occupancy can rise (256 x 6).
// Streaming cache hints since no data is ever reused.

static __device__ __forceinline__ float onehot_val(int j, int s, float tiny) {
    if (j == s) return 1.0f;
    if (((j ^ s) & 0xF0) == 0 || ((j ^ s) & 0x0F) == 0) return tiny;
    return 0.0f;
}

__global__ void __launch_bounds__(256, 6) moe_alu_kernel(
    const float4* __restrict__ a4,
    const float4* __restrict__ b4,
    float4* __restrict__ o4,
    int B)
{
    const int warp = blockIdx.x * (blockDim.x >> 5) + (threadIdx.x >> 5);
    const int lane = threadIdx.x & 31;
    if (warp >= B) return;

    const float4* __restrict__ pa = a4 + (size_t)warp * 256;
    const float4* __restrict__ pb = b4 + (size_t)warp * 256;

    // Decode: slot s = r>>1 is compile-time uniform per iteration.
    // acc[s] = sum over its 256 one-hot floats of val * byte_index
    //        = the byte index itself (index 0 contributes 0, which is
    //          already correct for the OR-pack below).
    float accA[4] = {0.f, 0.f, 0.f, 0.f};
    float accB[4] = {0.f, 0.f, 0.f, 0.f};
    #pragma unroll
    for (int r = 0; r < 8; r++) {
        const int   f4 = lane + 32 * r;
        const float j  = (float)(lane * 4 + 128 * (r & 1)); // byte idx of .x
        const float4 xa = __ldcs(pa + f4);
        const float4 xb = __ldcs(pb + f4);
        const int s = r >> 1;
        accA[s] += xa.x * j + xa.y * (j + 1.f) + xa.z * (j + 2.f) + xa.w * (j + 3.f);
        accB[s] += xb.x * j + xb.y * (j + 1.f) + xb.z * (j + 2.f) + xb.w * (j + 3.f);
    }

    // Pack the 4 byte values (each lane holds 0 or the true byte, exactly
    // representable) and OR-reduce across the warp.
    unsigned ia = (unsigned)(int)accA[0]
                | ((unsigned)(int)accA[1] << 8)
                | ((unsigned)(int)accA[2] << 16)
                | ((unsigned)(int)accA[3] << 24);
    unsigned ib = (unsigned)(int)accB[0]
                | ((unsigned)(int)accB[1] << 8)
                | ((unsigned)(int)accB[2] << 16)
                | ((unsigned)(int)accB[3] << 24);
    const unsigned va = __reduce_or_sync(0xFFFFFFFFu, ia);
    const unsigned vb = __reduce_or_sync(0xFFFFFFFFu, ib);

    const unsigned vsum = va + vb;   // LE 4-byte carry chain == u32 add
    const unsigned vxor = va ^ vb;

    const float TINY = 3.7200760e-44f;   // expf(-100) as fp32 subnormal

    float4* __restrict__ po_add = o4 + (size_t)warp * 256;
    float4* __restrict__ po_xor = o4 + ((size_t)B + warp) * 256;

    #pragma unroll
    for (int r = 0; r < 8; r++) {
        const int f4 = lane + 32 * r;
        const int j  = lane * 4 + 128 * (r & 1);   // byte idx of component .x
        const int sh = (r >> 1) * 8;
        const int ss = (int)((vsum >> sh) & 255u);
        const int xs = (int)((vxor >> sh) & 255u);
        float4 oa, ox;
        oa.x = onehot_val(j    , ss, TINY);
        oa.y = onehot_val(j + 1, ss, TINY);
        oa.z = onehot_val(j + 2, ss, TINY);
        oa.w = onehot_val(j + 3, ss, TINY);
        ox.x = onehot_val(j    , xs, TINY);
        ox.y = onehot_val(j + 1, xs, TINY);
        ox.z = onehot_val(j + 2, xs, TINY);
        ox.w = onehot_val(j + 3, xs, TINY);
        __stcs(po_add + f4, oa);
        __stcs(po_xor + f4, ox);
    }
}

extern "C" void kernel_launch(void* const* d_in, const int* in_sizes, int n_in,
                              void* d_out, int out_size)
{
    const float4* a = (const float4*)d_in[0];
    const float4* b = (const float4*)d_in[1];
    float4* out = (float4*)d_out;

    const int B = in_sizes[0] / 1024;          // inputs are [B,4,256] floats
    const int threads = 256;                   // 8 warps per block
    const int blocks = (B * 32 + threads - 1) / threads;
    moe_alu_kernel<<<blocks, threads>>>(a, b, out, B);
}